// round 1
// baseline (speedup 1.0000x reference)
#include <cuda_runtime.h>
#include <cuda_bf16.h>

// Conv2D 3x3 SAME stride-1: x [16,128,128,64] NHWC fp32, w [3,3,64,128] HWIO,
// bias [128], out [16,128,128,128] fp32.
// Implicit GEMM: one CTA = one output row (n,h): 128 pixels x 128 couts,
// K = 9 steps of 64 cin each. fp32 FFMA baseline.

#define CH    128
#define CW    128
#define CIN   64
#define COUT  128
#define AS_STRIDE 65   // pad to avoid smem bank conflicts

// smem: As[128][65] + Bs[64][128]
#define AS_ELEMS (CW * AS_STRIDE)
#define BS_ELEMS (CIN * COUT)
#define SMEM_BYTES ((AS_ELEMS + BS_ELEMS) * 4)

__global__ __launch_bounds__(256, 2)
void conv3x3_rowtile_kernel(const float* __restrict__ x,
                            const float* __restrict__ wt,
                            const float* __restrict__ bias,
                            float* __restrict__ out) {
    extern __shared__ float smem[];
    float* As = smem;              // [w][c] : 128 x 65
    float* Bs = smem + AS_ELEMS;   // [c][co]: 64 x 128

    const int tid = threadIdx.x;
    const int tx = tid & 15;       // cout group (8 couts)
    const int ty = tid >> 4;       // pixel group (8 pixels)

    const int bx = blockIdx.x;     // n*H + h
    const int n  = bx >> 7;
    const int h  = bx & 127;

    const float* xn = x + (size_t)n * CH * CW * CIN;

    float acc[8][8];
#pragma unroll
    for (int i = 0; i < 8; ++i)
#pragma unroll
        for (int j = 0; j < 8; ++j) acc[i][j] = 0.0f;

    for (int t = 0; t < 9; ++t) {
        const int kh = t / 3;
        const int kw = t - kh * 3;
        const int hr = h + kh - 1;
        const bool rowok = (hr >= 0) && (hr < CH);
        const float* xrow = xn + (size_t)hr * CW * CIN;
        const float* wsl  = wt + (size_t)t * CIN * COUT;

        __syncthreads();   // protect smem from previous iteration's readers

        // Stage A: 128 pixels x 64 cin, shifted by (kw-1), zero padded.
        // flat = pixel*64 + c -> coalesced 256B segments per 64 threads.
#pragma unroll
        for (int i = 0; i < 32; ++i) {
            const int flat = tid + i * 256;
            const int c  = flat & 63;
            const int w  = flat >> 6;
            const int wc = w + kw - 1;
            float v = 0.0f;
            if (rowok && (unsigned)wc < (unsigned)CW)
                v = xrow[wc * CIN + c];
            As[w * AS_STRIDE + c] = v;
        }
        // Stage B: weight slice [64][128], contiguous in gmem.
#pragma unroll
        for (int i = 0; i < 32; ++i) {
            const int flat = tid + i * 256;
            Bs[flat] = wsl[flat];
        }
        __syncthreads();

        // 128x128x64 GEMM, 8x8 micro-tile per thread.
#pragma unroll 8
        for (int kk = 0; kk < CIN; ++kk) {
            float a[8];
#pragma unroll
            for (int i = 0; i < 8; ++i)
                a[i] = As[(ty * 8 + i) * AS_STRIDE + kk];
            float b[8];
            const float4 b0 = *(const float4*)&Bs[kk * COUT + tx * 8];
            const float4 b1 = *(const float4*)&Bs[kk * COUT + tx * 8 + 4];
            b[0] = b0.x; b[1] = b0.y; b[2] = b0.z; b[3] = b0.w;
            b[4] = b1.x; b[5] = b1.y; b[6] = b1.z; b[7] = b1.w;
#pragma unroll
            for (int i = 0; i < 8; ++i)
#pragma unroll
                for (int j = 0; j < 8; ++j)
                    acc[i][j] = fmaf(a[i], b[j], acc[i][j]);
        }
    }

    // Epilogue: add bias, store 8 pixels x 8 couts per thread (float4).
    float bv[8];
#pragma unroll
    for (int j = 0; j < 8; ++j) bv[j] = bias[tx * 8 + j];

    float* orow = out + (size_t)bx * CW * COUT;   // (n*H + h) row base
#pragma unroll
    for (int i = 0; i < 8; ++i) {
        const int wpix = ty * 8 + i;
        float4 o0, o1;
        o0.x = acc[i][0] + bv[0];
        o0.y = acc[i][1] + bv[1];
        o0.z = acc[i][2] + bv[2];
        o0.w = acc[i][3] + bv[3];
        o1.x = acc[i][4] + bv[4];
        o1.y = acc[i][5] + bv[5];
        o1.z = acc[i][6] + bv[6];
        o1.w = acc[i][7] + bv[7];
        *(float4*)&orow[wpix * COUT + tx * 8]     = o0;
        *(float4*)&orow[wpix * COUT + tx * 8 + 4] = o1;
    }
}

extern "C" void kernel_launch(void* const* d_in, const int* in_sizes, int n_in,
                              void* d_out, int out_size) {
    const float* x    = (const float*)d_in[0];
    const float* wt   = (const float*)d_in[1];
    const float* bias = (const float*)d_in[2];
    float* out = (float*)d_out;

    cudaFuncSetAttribute(conv3x3_rowtile_kernel,
                         cudaFuncAttributeMaxDynamicSharedMemorySize, SMEM_BYTES);

    const int nbatch = in_sizes[0] / (CH * CW * CIN);   // 16
    dim3 grid(nbatch * CH);                             // 2048 CTAs (one per row)
    conv3x3_rowtile_kernel<<<grid, 256, SMEM_BYTES>>>(x, wt, bias, out);
}

// round 3
// speedup vs baseline: 3.4609x; 3.4609x over previous
#include <cuda_runtime.h>
#include <cstdint>

// Conv2D 3x3 SAME stride-1 via mma.sync.m16n8k8.tf32 implicit GEMM.
// x [16,128,128,64] NHWC fp32, w [3,3,64,128] HWIO, bias [128] -> out [16,128,128,128] fp32.
// CTA = 2 output rows: M=256 pixels x N=128 couts, K = 9 taps x 64 cin.
// A staged once with +/-1 pixel halo; tap shift = address offset at frag load.

#define CH 128
#define CW 128
#define CIN 64
#define COUT 128

#define AP 68                   // As pixel-row stride (words), conflict-free frag loads
#define BP 68                   // Bs cout-row stride (words)
#define A_PLANE (130 * AP)      // 130 pixel rows (halo) x 68
#define AS_WORDS (4 * A_PLANE)
#define BS_WORDS (2 * COUT * BP)
#define SMEM_BYTES ((AS_WORDS + BS_WORDS) * 4)   // 211,072 B

static __device__ __forceinline__ uint32_t cvt_tf32(float f) {
    uint32_t r; asm("cvt.rna.tf32.f32 %0, %1;" : "=r"(r) : "f"(f)); return r;
}

#define MMA_TF32(c, a, b) \
    asm volatile("mma.sync.aligned.m16n8k8.row.col.f32.tf32.tf32.f32 " \
        "{%0,%1,%2,%3}, {%4,%5,%6,%7}, {%8,%9}, {%0,%1,%2,%3};" \
        : "+f"((c)[0]), "+f"((c)[1]), "+f"((c)[2]), "+f"((c)[3]) \
        : "r"((a)[0]), "r"((a)[1]), "r"((a)[2]), "r"((a)[3]), \
          "r"((b)[0]), "r"((b)[1]))

__global__ __launch_bounds__(256, 1)
void conv3x3_mma_kernel(const float* __restrict__ x,
                        const float* __restrict__ wt,
                        const float* __restrict__ bias,
                        float* __restrict__ out) {
    extern __shared__ uint32_t smem[];
    uint32_t* As = smem;                 // [plane 0..3][pixel -1..128 -> 0..129][cin]
    uint32_t* Bs = smem + AS_WORDS;      // [buf 0..1][cout][cin]

    const int tid  = threadIdx.x;
    const int wid  = tid >> 5;
    const int lane = tid & 31;
    const int gid  = lane >> 2;          // 0..7
    const int t4   = lane & 3;           // 0..3

    const int warp_m = wid >> 1;         // 0..3 : m offset 64*warp_m over M=256
    const int warp_n = wid & 1;          // 0..1 : n offset 64*warp_n

    const int bx = blockIdx.x;
    const int n  = bx >> 6;
    const int h0 = (bx & 63) << 1;       // output rows h0, h0+1

    // ---- stage A: 4 input row planes (h0-1 .. h0+2), tf32, zero halo ----
    const float* xn = x + (size_t)n * CH * CW * CIN;
#pragma unroll
    for (int r = 0; r < 4; ++r) {
        const int hr = h0 - 1 + r;
        uint32_t* plane = As + r * A_PLANE;
        if ((unsigned)hr < (unsigned)CH) {
            const float4* xrow = (const float4*)(xn + (size_t)hr * CW * CIN);
#pragma unroll
            for (int i = 0; i < 8; ++i) {
                const int f4  = i * 256 + tid;      // 0..2047
                const int pix = f4 >> 4;
                const int c4  = (f4 & 15) << 2;
                const float4 v = xrow[f4];
                uint32_t* d = plane + (pix + 1) * AP + c4;
                d[0] = cvt_tf32(v.x); d[1] = cvt_tf32(v.y);
                d[2] = cvt_tf32(v.z); d[3] = cvt_tf32(v.w);
            }
            if (tid < 2 * AP) {                      // zero halo rows -1 and 128
                const int row = (tid < AP) ? 0 : 129;
                const int c   = (tid < AP) ? tid : tid - AP;
                plane[row * AP + c] = 0;
            }
        } else {
            for (int i = tid; i < A_PLANE; i += 256) plane[i] = 0;
        }
    }

    // ---- stage W tap 0 into buffer 0 ----
    float wreg[32];
    {
#pragma unroll
        for (int i = 0; i < 32; ++i) wreg[i] = wt[i * 256 + tid];
#pragma unroll
        for (int i = 0; i < 32; ++i) {
            const int flat = i * 256 + tid;          // k*128 + n
            Bs[(flat & 127) * BP + (flat >> 7)] = cvt_tf32(wreg[i]);
        }
    }
    __syncthreads();

    float acc[4][8][4];
#pragma unroll
    for (int mi = 0; mi < 4; ++mi)
#pragma unroll
        for (int ni = 0; ni < 8; ++ni)
#pragma unroll
            for (int q = 0; q < 4; ++q) acc[mi][ni][q] = 0.0f;

    const int apix     = ((warp_m & 1) << 6) + gid;  // base pixel within row
    const int arow_sel = warp_m >> 1;                // which of the 2 output rows

    // ---- mainloop: 9 taps ----
    for (int t = 0; t < 9; ++t) {
        const int kh = (t >= 6) ? 2 : ((t >= 3) ? 1 : 0);
        const int kw = t - 3 * kh;

        if (t < 8) {   // prefetch next tap's weights into registers
            const float* wn = wt + (size_t)(t + 1) * CIN * COUT;
#pragma unroll
            for (int i = 0; i < 32; ++i) wreg[i] = wn[i * 256 + tid];
        }

        const uint32_t* ap = As + (arow_sel + kh) * A_PLANE + (apix + kw) * AP + t4;
        const uint32_t* bp = Bs + (t & 1) * COUT * BP + (warp_n * 64 + gid) * BP + t4;

#pragma unroll
        for (int ks = 0; ks < 8; ++ks) {
            const int cb = ks * 8;
            uint32_t a[4][4];
#pragma unroll
            for (int mi = 0; mi < 4; ++mi) {
                const uint32_t* p = ap + mi * 16 * AP + cb;
                a[mi][0] = p[0];
                a[mi][1] = p[8 * AP];
                a[mi][2] = p[4];
                a[mi][3] = p[8 * AP + 4];
            }
            uint32_t b[8][2];
#pragma unroll
            for (int ni = 0; ni < 8; ++ni) {
                const uint32_t* p = bp + ni * 8 * BP + cb;
                b[ni][0] = p[0];
                b[ni][1] = p[4];
            }
#pragma unroll
            for (int mi = 0; mi < 4; ++mi)
#pragma unroll
                for (int ni = 0; ni < 8; ++ni)
                    MMA_TF32(acc[mi][ni], a[mi], b[ni]);
        }

        if (t < 8) {   // store prefetched weights into the other buffer
            uint32_t* bd = Bs + ((t + 1) & 1) * COUT * BP;
#pragma unroll
            for (int i = 0; i < 32; ++i) {
                const int flat = i * 256 + tid;
                bd[(flat & 127) * BP + (flat >> 7)] = cvt_tf32(wreg[i]);
            }
        }
        __syncthreads();
    }

    // ---- epilogue: bias + store (register accumulators, no sync needed) ----
    const int hrow = h0 + arow_sel;
    float* orow = out + ((size_t)n * CH + hrow) * CW * COUT;
    const int pixb = ((warp_m & 1) << 6) + gid;
    const int nb   = warp_n * 64 + t4 * 2;

    float2 bv[8];
#pragma unroll
    for (int ni = 0; ni < 8; ++ni)
        bv[ni] = *(const float2*)&bias[nb + ni * 8];

#pragma unroll
    for (int mi = 0; mi < 4; ++mi) {
        const int p0 = pixb + mi * 16;
#pragma unroll
        for (int ni = 0; ni < 8; ++ni) {
            const int cout = nb + ni * 8;
            float2 v0, v1;
            v0.x = acc[mi][ni][0] + bv[ni].x;
            v0.y = acc[mi][ni][1] + bv[ni].y;
            v1.x = acc[mi][ni][2] + bv[ni].x;
            v1.y = acc[mi][ni][3] + bv[ni].y;
            *(float2*)&orow[(size_t)p0 * COUT + cout]       = v0;
            *(float2*)&orow[(size_t)(p0 + 8) * COUT + cout] = v1;
        }
    }
}

extern "C" void kernel_launch(void* const* d_in, const int* in_sizes, int n_in,
                              void* d_out, int out_size) {
    const float* x    = (const float*)d_in[0];
    const float* wt   = (const float*)d_in[1];
    const float* bias = (const float*)d_in[2];
    float* out = (float*)d_out;

    cudaFuncSetAttribute(conv3x3_mma_kernel,
                         cudaFuncAttributeMaxDynamicSharedMemorySize, SMEM_BYTES);

    const int nbatch = in_sizes[0] / (CH * CW * CIN);   // 16
    dim3 grid(nbatch * (CH / 2));                       // 1024 CTAs
    conv3x3_mma_kernel<<<grid, 256, SMEM_BYTES>>>(x, wt, bias, out);
}